// round 13
// baseline (speedup 1.0000x reference)
#include <cuda_runtime.h>
#include <cuda_fp16.h>
#include <cstdint>

// feats[n,f] = sum_{pq} k0[n,p] IF[f,p,q] k1[n,q].  Points sorted by 14x14 bin,
// bin-rows chopped into 128-pt CTAs; 16x16 (p,q) windows precomputed in the
// plan kernel from covered-bin bounds. fp16 m16n8k16 mma.sync, fp32 acc.
// R13: exp tables via 1-exp-per-8-entries recurrence (MUFU 4096 -> ~1.5K/CTA),
// windows+{start,end} in one int4 (B gather issues immediately), scatter also
// packs coords, prep chain 4 launches.

#define PP 28
#define FDIM 128
#define NBIN 14
#define NBIN2 196
#define WIN 16
#define KSTEPS 16
#define NTHREADS 512
#define ROWB 528             // 33 16B units (odd -> conflict-free ldmatrix)
#define TENB (128 * ROWB)
#define MAXPTS 131072
#define MAXCTA ((MAXPTS / 128) + NBIN)
#define BINTHREADS 1024
#define HISTBLOCKS 128
#define NVAR 7               // wq in {0,2,...,12}
#define VARELEM (FDIM * PP * WIN)          // 57344 halfs per variant
#define CONVBLOCKS ((NVAR * VARELEM) / BINTHREADS)  // 392

// smem offsets (main kernel)
#define OFF_A   0
#define OFF_B   TENB
#define OFF_K0  (2 * TENB)                  // k0s[WIN][129] float
#define OFF_K1  (OFF_K0 + WIN * 129 * 4)
#define OFF_XS  (OFF_K1 + WIN * 129 * 4)    // xs[256] float
#define OFF_IDX (OFF_XS + 1024)             // sidx[128] int
#define SMEM_TOT (OFF_IDX + 512)            // 153216

#define G0 0.001f
#define GH (0.998f / 27.0f)

static __device__ __align__(16) __half g_Bvar[NVAR * VARELEM];  // [v][f][p][16]
static __device__ int   g_cntPart[HISTBLOCKS * NBIN2];
static __device__ int   g_fill[NBIN2];
static __device__ int   g_off[NBIN2];
static __device__ int   g_ptidx[MAXPTS];
static __device__ float2 g_px[MAXPTS];
static __device__ int4  g_ctaInfo[MAXCTA];   // {start, end, wp, wq}
static __device__ int   g_nCta;

__device__ __forceinline__ uint32_t smem_u32(const void* p) {
    uint32_t a;
    asm("{ .reg .u64 t; cvta.to.shared.u64 t, %1; cvt.u32.u64 %0, t; }" : "=r"(a) : "l"(p));
    return a;
}
#define LDSM4(r0, r1, r2, r3, a)                                               \
    asm volatile("ldmatrix.sync.aligned.m8n8.x4.shared.b16 {%0,%1,%2,%3}, [%4];" \
                 : "=r"(r0), "=r"(r1), "=r"(r2), "=r"(r3) : "r"(a))
#define MMA16816(d, a, b0, b1)                                                 \
    asm volatile("mma.sync.aligned.m16n8k16.row.col.f32.f16.f16.f32 "          \
                 "{%0,%1,%2,%3}, {%4,%5,%6,%7}, {%8,%9}, {%0,%1,%2,%3};"       \
                 : "+f"((d)[0]), "+f"((d)[1]), "+f"((d)[2]), "+f"((d)[3])      \
                 : "r"((a)[0]), "r"((a)[1]), "r"((a)[2]), "r"((a)[3]),         \
                   "r"(b0), "r"(b1))
#define CPASYNC16(dst, src)                                                    \
    asm volatile("cp.async.cg.shared.global [%0], [%1], 16;" :: "r"(dst), "l"(src))

__device__ __forceinline__ int bin_of(float v) {
    int b = (int)(v * NBIN);
    return b < 0 ? 0 : (b > NBIN - 1 ? NBIN - 1 : b);
}

// ---- 1: partial histograms + build repacked B variants (fused, no pre-zero) ----
__global__ __launch_bounds__(BINTHREADS)
void init_count_kernel(const float* __restrict__ IF,
                       const float* __restrict__ x, int n) {
    const int tid = threadIdx.x;
    if (blockIdx.x < HISTBLOCKS) {
        __shared__ int scnt[NBIN2];
        if (tid < NBIN2) scnt[tid] = 0;
        __syncthreads();
        const int i = blockIdx.x * BINTHREADS + tid;
        if (i < n) {
            float2 xv = reinterpret_cast<const float2*>(x)[i];
            atomicAdd(&scnt[bin_of(xv.y) * NBIN + bin_of(xv.x)], 1);
        }
        __syncthreads();
        if (tid < NBIN2) g_cntPart[blockIdx.x * NBIN2 + tid] = scnt[tid];
    } else {
        const int idx = (blockIdx.x - HISTBLOCKS) * BINTHREADS + tid;
        if (idx < NVAR * VARELEM) {
            const int v   = idx / VARELEM;
            const int rem = idx - v * VARELEM;
            const int f   = rem / (PP * WIN);
            const int r2  = rem - f * (PP * WIN);
            const int p   = r2 >> 4;
            const int qi  = r2 & 15;
            const int q   = 2 * v + qi;
            g_Bvar[idx] = __float2half(IF[f * (PP * PP) + p * PP + q]);
        }
    }
}

// ---- 2: sum partials, prefix, zero g_fill, row-chopped CTA plan + windows ----
__global__ void plan_kernel() {
    __shared__ int scnt[NBIN2];
    __shared__ int rowOff[NBIN], rowCnt[NBIN], rowCtaOff[NBIN];
    const int t = threadIdx.x;
    if (t < NBIN2) {
        int s = 0;
        for (int b = 0; b < HISTBLOCKS; b++) s += g_cntPart[b * NBIN2 + t];
        scnt[t] = s;
        g_fill[t] = 0;
    }
    __syncthreads();
    if (t == 0) {
        int op = 0;
        for (int b = 0; b < NBIN2; b++) { g_off[b] = op; op += scnt[b]; }
        int oc = 0;
        for (int r = 0; r < NBIN; r++) {
            int rc = 0;
            for (int bx = 0; bx < NBIN; bx++) rc += scnt[r * NBIN + bx];
            rowOff[r] = g_off[r * NBIN];
            rowCnt[r] = rc;
            rowCtaOff[r] = oc;
            oc += (rc + 127) >> 7;
        }
        g_nCta = oc;
    }
    __syncthreads();
    if (t < NBIN) {
        const int r = t;
        const int rEnd = rowOff[r] + rowCnt[r];
        const int nc = (rowCnt[r] + 127) >> 7;
        // row q-window (same formula as the per-bin R10 version)
        int wq = (int)floorf(((r + 0.5f) / NBIN - G0) / GH) - 7;
        wq = (wq < 0 ? 0 : (wq > PP - WIN ? PP - WIN : wq)) & ~1;
        int bx = 0;
        for (int j = 0; j < nc; j++) {
            const int s = rowOff[r] + (j << 7);
            const int e = min(s + 128, rEnd);
            // advance bx to the bin containing s
            while (bx < NBIN - 1 && g_off[r * NBIN + bx + 1] <= s) bx++;
            int bx1 = bx;
            while (bx1 < NBIN - 1 && g_off[r * NBIN + bx1 + 1] < e) bx1++;
            const float xlo = (float)bx / NBIN;
            const float xhi = (float)(bx1 + 1) / NBIN;
            int wp = (int)floorf((0.5f * (xlo + xhi) - G0) / GH) - 7;
            wp = wp < 0 ? 0 : (wp > PP - WIN ? PP - WIN : wp);
            g_ctaInfo[rowCtaOff[r] + j] = make_int4(s, e, wp, wq);
        }
    }
}

// ---- 3: scatter indices + packed coords, smem-aggregated ----
__global__ __launch_bounds__(BINTHREADS)
void scatter_kernel(const float* __restrict__ x, int n) {
    __shared__ int scnt[NBIN2];
    __shared__ int sbase[NBIN2];
    const int tid = threadIdx.x;
    if (tid < NBIN2) scnt[tid] = 0;
    __syncthreads();
    const int i = blockIdx.x * BINTHREADS + tid;
    int b = -1, lpos = 0;
    float2 xv = make_float2(0.f, 0.f);
    if (i < n) {
        xv = reinterpret_cast<const float2*>(x)[i];
        b = bin_of(xv.y) * NBIN + bin_of(xv.x);
        lpos = atomicAdd(&scnt[b], 1);
    }
    __syncthreads();
    if (tid < NBIN2 && scnt[tid] > 0)
        sbase[tid] = atomicAdd(&g_fill[tid], scnt[tid]);
    __syncthreads();
    if (b >= 0) {
        const int pos = g_off[b] + sbase[b] + lpos;
        g_ptidx[pos] = i;
        g_px[pos]    = xv;
    }
}

// ---- 4: main GEMM ----
__global__ __launch_bounds__(NTHREADS, 1)
void image_features_bin_kernel(const float* __restrict__ sigma,
                               float* __restrict__ out)
{
    const int bid = blockIdx.x;
    if (bid >= g_nCta) return;

    extern __shared__ unsigned char smem[];
    const uint32_t sb = smem_u32(smem);

    const int tid  = threadIdx.x;
    const int lane = tid & 31;
    const int w    = tid >> 5;
    const int wm   = w >> 2;
    const int wn   = w & 3;

    const int4 inf = g_ctaInfo[bid];     // {start, end, wp, wq}
    const int start = inf.x;
    const int nloc  = inf.y - inf.x;     // <= 128 by construction
    const int wp = inf.z, wq = inf.w;

    float* xs   = reinterpret_cast<float*>(smem + OFF_XS);
    float* k0s  = reinterpret_cast<float*>(smem + OFF_K0);
    float* k1s  = reinterpret_cast<float*>(smem + OFF_K1);
    int*   sidx = reinterpret_cast<int*>(smem + OFF_IDX);

    // B gather: per f a contiguous 512B block; 4096 x 16B cp.async
    {
        const __half* vbase = g_Bvar + (size_t)(wq >> 1) * VARELEM + wp * WIN;
        #pragma unroll
        for (int j = 0; j < 8; j++) {
            const int u = tid + j * NTHREADS;
            const int f = u >> 5;
            const int c = u & 31;
            const uint32_t dst = sb + OFF_B + f * ROWB + (c >> 1) * 32 + (c & 1) * 16;
            CPASYNC16(dst, vbase + f * (PP * WIN) + c * 8);
        }
        asm volatile("cp.async.commit_group;" ::: "memory");
    }

    // point gather (coords packed by scatter; pad rows reuse last point)
    if (tid < 128) {
        const int pos = start + min(tid, nloc - 1);
        sidx[tid] = (tid < nloc) ? g_ptidx[pos] : -1;
        const float2 xv = g_px[pos];
        xs[2 * tid]     = xv.x;
        xs[2 * tid + 1] = xv.y;
    }

    const float ls  = __expf(sigma[0]);
    const float inv = 0.5f / (ls * ls);
    __syncthreads();   // xs visible

    // exp tables via recurrence: thread = (m, axis, half); 8 entries each.
    // k(i)=exp(-inv*d(i)^2), d(i)=d0+i*GH; k*=t, t*=S per step.
    {
        const int m    = tid & 127;
        const int axis = (tid >> 7) & 1;
        const int i0   = (tid >> 8) * 8;
        const int wnd  = axis ? wq : wp;
        const float xv = xs[2 * m + axis];
        const float d0 = (G0 + (float)(wnd + i0) * GH) - xv;
        const float S  = __expf(-2.0f * inv * GH * GH);
        float k = __expf(-inv * d0 * d0);
        float t = __expf(-inv * GH * (2.0f * d0 + GH));
        float* tab = (axis ? k1s : k0s) + i0 * 129 + m;
        #pragma unroll
        for (int i = 0; i < 8; i++) {
            tab[i * 129] = k;
            k *= t;
            t *= S;
        }
    }
    __syncthreads();   // tables visible

    // A build: A[m][pi*16+qi] = k0s[pi][m] * k1s[qi][m]
    {
        const int m   = tid >> 2;
        const int sub = tid & 3;
        unsigned char* Ab = smem + OFF_A;
        #pragma unroll
        for (int pi = 0; pi < WIN; pi++) {
            const float k0v = k0s[pi * 129 + m];
            #pragma unroll
            for (int qq = 0; qq < 2; qq++) {
                const int q = sub * 4 + 2 * qq;
                const float pr0 = k0v * k1s[q * 129 + m];
                const float pr1 = k0v * k1s[(q + 1) * 129 + m];
                __half2 hv = __floats2half2_rn(pr0, pr1);
                *reinterpret_cast<uint32_t*>(Ab + m * ROWB + (pi * 16 + q) * 2) =
                    *reinterpret_cast<uint32_t*>(&hv);
            }
        }
    }
    asm volatile("cp.async.wait_group 0;" ::: "memory");
    __syncthreads();   // A + B ready

    float acc[2][4][4];
    #pragma unroll
    for (int i = 0; i < 2; i++)
        #pragma unroll
        for (int j = 0; j < 4; j++)
            #pragma unroll
            for (int k = 0; k < 4; k++) acc[i][j][k] = 0.0f;

    const uint32_t sA = sb + OFF_A;
    const uint32_t sB = sb + OFF_B;
    const uint32_t aoff = (lane & 15) * ROWB + (((lane >> 4) << 3) * 2);

    #pragma unroll 4
    for (int s = 0; s < KSTEPS; s++) {
        const uint32_t kboff = s * 32;

        uint32_t ah[2][4];
        #pragma unroll
        for (int i = 0; i < 2; i++) {
            const uint32_t aa = sA + (wm * 32 + i * 16) * ROWB + aoff + kboff;
            LDSM4(ah[i][0], ah[i][1], ah[i][2], ah[i][3], aa);
        }
        uint32_t bh[2][4];
        #pragma unroll
        for (int g = 0; g < 2; g++) {
            const uint32_t ba = sB + (wn * 32 + g * 16) * ROWB + aoff + kboff;
            LDSM4(bh[g][0], bh[g][1], bh[g][2], bh[g][3], ba);
        }
        #pragma unroll
        for (int i = 0; i < 2; i++)
            #pragma unroll
            for (int j = 0; j < 4; j++) {
                const int jg = j >> 1, par = j & 1;
                MMA16816(acc[i][j], ah[i], bh[jg][par], bh[jg][par + 2]);
            }
    }

    // epilogue: scatter rows via sidx
    #pragma unroll
    for (int i = 0; i < 2; i++) {
        const int r0 = wm * 32 + i * 16 + (lane >> 2);
        const int g0 = sidx[r0];
        const int g1 = sidx[r0 + 8];
        #pragma unroll
        for (int j = 0; j < 4; j++) {
            const int col = wn * 32 + j * 8 + 2 * (lane & 3);
            if (g0 >= 0)
                *reinterpret_cast<float2*>(out + (size_t)g0 * FDIM + col) =
                    make_float2(acc[i][j][0], acc[i][j][1]);
            if (g1 >= 0)
                *reinterpret_cast<float2*>(out + (size_t)g1 * FDIM + col) =
                    make_float2(acc[i][j][2], acc[i][j][3]);
        }
    }
}

extern "C" void kernel_launch(void* const* d_in, const int* in_sizes, int n_in,
                              void* d_out, int out_size)
{
    const float* x     = (const float*)d_in[0];   // [B, N, 2]
    const float* sigma = (const float*)d_in[1];   // [1]
    const float* IF    = (const float*)d_in[2];   // [F, P, P]
    float* out         = (float*)d_out;           // [B*N, F]

    const int n = in_sizes[0] / 2;                // 131072

    cudaFuncSetAttribute(image_features_bin_kernel,
                         cudaFuncAttributeMaxDynamicSharedMemorySize, SMEM_TOT);

    init_count_kernel<<<HISTBLOCKS + CONVBLOCKS, BINTHREADS>>>(IF, x, n);
    plan_kernel<<<1, 256>>>();
    scatter_kernel<<<(n + BINTHREADS - 1) / BINTHREADS, BINTHREADS>>>(x, n);
    image_features_bin_kernel<<<n / 128 + NBIN, NTHREADS, SMEM_TOT>>>(sigma, out);
}

// round 14
// speedup vs baseline: 1.2182x; 1.2182x over previous
#include <cuda_runtime.h>
#include <cuda_fp16.h>
#include <cstdint>

// feats[n,f] = sum_{pq} k0[n,p] IF[f,p,q] k1[n,q].  Points sorted by 14x14 bin,
// bin-rows chopped into 128-pt CTAs; 16x16 (p,q) windows precomputed in plan.
// fp16 m16n8k16 mma.sync, fp32 acc. R14: A fragments built in REGISTERS
// (kstep s == window row pi, so A = k0[s][m]*k1[c][m]; k1 factors hoisted as
// half2) -> no A smem tile, 153KB -> 85.6KB -> 2 CTAs/SM to hide prologue.

#define PP 28
#define FDIM 128
#define NBIN 14
#define NBIN2 196
#define WIN 16
#define KSTEPS 16
#define NTHREADS 512
#define ROWB 528             // 33 16B units (odd -> conflict-free ldmatrix)
#define MAXPTS 131072
#define MAXCTA ((MAXPTS / 128) + NBIN)
#define BINTHREADS 1024
#define HISTBLOCKS 128
#define NVAR 7               // wq in {0,2,...,12}
#define VARELEM (FDIM * PP * WIN)          // 57344 halfs per variant
#define CONVBLOCKS ((NVAR * VARELEM) / BINTHREADS)  // 392

// smem offsets (main kernel): B tile + fp32 exp tables + coords + indices
#define OFF_B   0                           // 128*528 = 67584
#define OFF_K0  67584                       // k0s[16][129] float = 8256
#define OFF_K1  75840                       // k1s[16][129] float = 8256
#define OFF_XS  84096                       // xs[256] float
#define OFF_IDX 85120                       // sidx[128] int
#define SMEM_TOT 85632                      // x2 CTAs = 171264 <= 228KB

#define G0 0.001f
#define GH (0.998f / 27.0f)

static __device__ __align__(16) __half g_Bvar[NVAR * VARELEM];  // [v][f][p][16]
static __device__ int    g_cnt[NBIN2];
static __device__ int    g_fill[NBIN2];
static __device__ int    g_off[NBIN2];
static __device__ int    g_ptidx[MAXPTS];
static __device__ float2 g_px[MAXPTS];
static __device__ int4   g_ctaInfo[MAXCTA];   // {start, end, wp, wq}
static __device__ int    g_nCta;

__device__ __forceinline__ uint32_t smem_u32(const void* p) {
    uint32_t a;
    asm("{ .reg .u64 t; cvta.to.shared.u64 t, %1; cvt.u32.u64 %0, t; }" : "=r"(a) : "l"(p));
    return a;
}
#define LDSM4(r0, r1, r2, r3, a)                                               \
    asm volatile("ldmatrix.sync.aligned.m8n8.x4.shared.b16 {%0,%1,%2,%3}, [%4];" \
                 : "=r"(r0), "=r"(r1), "=r"(r2), "=r"(r3) : "r"(a))
#define MMA16816(d, a0, a1, a2, a3, b0, b1)                                    \
    asm volatile("mma.sync.aligned.m16n8k16.row.col.f32.f16.f16.f32 "          \
                 "{%0,%1,%2,%3}, {%4,%5,%6,%7}, {%8,%9}, {%0,%1,%2,%3};"       \
                 : "+f"((d)[0]), "+f"((d)[1]), "+f"((d)[2]), "+f"((d)[3])      \
                 : "r"(a0), "r"(a1), "r"(a2), "r"(a3), "r"(b0), "r"(b1))
#define CPASYNC16(dst, src)                                                    \
    asm volatile("cp.async.cg.shared.global [%0], [%1], 16;" :: "r"(dst), "l"(src))

__device__ __forceinline__ int bin_of(float v) {
    int b = (int)(v * NBIN);
    return b < 0 ? 0 : (b > NBIN - 1 ? NBIN - 1 : b);
}

// ---- 0: zero counters ----
__global__ void zero_kernel() {
    int t = threadIdx.x;
    if (t < NBIN2) { g_cnt[t] = 0; g_fill[t] = 0; }
}

// ---- 1: histogram (smem-aggregated atomics) + build B variants (fused) ----
__global__ __launch_bounds__(BINTHREADS)
void init_count_kernel(const float* __restrict__ IF,
                       const float* __restrict__ x, int n) {
    const int tid = threadIdx.x;
    if (blockIdx.x < HISTBLOCKS) {
        __shared__ int scnt[NBIN2];
        if (tid < NBIN2) scnt[tid] = 0;
        __syncthreads();
        const int i = blockIdx.x * BINTHREADS + tid;
        if (i < n) {
            float2 xv = reinterpret_cast<const float2*>(x)[i];
            atomicAdd(&scnt[bin_of(xv.y) * NBIN + bin_of(xv.x)], 1);
        }
        __syncthreads();
        if (tid < NBIN2 && scnt[tid] > 0) atomicAdd(&g_cnt[tid], scnt[tid]);
    } else {
        const int idx = (blockIdx.x - HISTBLOCKS) * BINTHREADS + tid;
        if (idx < NVAR * VARELEM) {
            const int v   = idx / VARELEM;
            const int rem = idx - v * VARELEM;
            const int f   = rem / (PP * WIN);
            const int r2  = rem - f * (PP * WIN);
            const int p   = r2 >> 4;
            const int qi  = r2 & 15;
            g_Bvar[idx] = __float2half(IF[f * (PP * PP) + p * PP + 2 * v + qi]);
        }
    }
}

// ---- 2: prefix + row-chopped CTA plan with windows ----
__global__ void plan_kernel() {
    __shared__ int scnt[NBIN2];
    __shared__ int rowOff[NBIN], rowCnt[NBIN], rowCtaOff[NBIN];
    const int t = threadIdx.x;
    if (t < NBIN2) scnt[t] = g_cnt[t];
    __syncthreads();
    if (t == 0) {
        int op = 0;
        for (int b = 0; b < NBIN2; b++) { g_off[b] = op; op += scnt[b]; }
        int oc = 0;
        for (int r = 0; r < NBIN; r++) {
            int rc = 0;
            for (int bx = 0; bx < NBIN; bx++) rc += scnt[r * NBIN + bx];
            rowOff[r] = g_off[r * NBIN];
            rowCnt[r] = rc;
            rowCtaOff[r] = oc;
            oc += (rc + 127) >> 7;
        }
        g_nCta = oc;
    }
    __syncthreads();
    if (t < NBIN) {
        const int r = t;
        const int rEnd = rowOff[r] + rowCnt[r];
        const int nc = (rowCnt[r] + 127) >> 7;
        int wq = (int)floorf(((r + 0.5f) / NBIN - G0) / GH) - 7;
        wq = (wq < 0 ? 0 : (wq > PP - WIN ? PP - WIN : wq)) & ~1;
        int bx = 0;
        for (int j = 0; j < nc; j++) {
            const int s = rowOff[r] + (j << 7);
            const int e = min(s + 128, rEnd);
            while (bx < NBIN - 1 && g_off[r * NBIN + bx + 1] <= s) bx++;
            int bx1 = bx;
            while (bx1 < NBIN - 1 && g_off[r * NBIN + bx1 + 1] < e) bx1++;
            const float xlo = (float)bx / NBIN;
            const float xhi = (float)(bx1 + 1) / NBIN;
            int wp = (int)floorf((0.5f * (xlo + xhi) - G0) / GH) - 7;
            wp = wp < 0 ? 0 : (wp > PP - WIN ? PP - WIN : wp);
            g_ctaInfo[rowCtaOff[r] + j] = make_int4(s, e, wp, wq);
        }
    }
}

// ---- 3: scatter indices + packed coords, smem-aggregated ----
__global__ __launch_bounds__(BINTHREADS)
void scatter_kernel(const float* __restrict__ x, int n) {
    __shared__ int scnt[NBIN2];
    __shared__ int sbase[NBIN2];
    const int tid = threadIdx.x;
    if (tid < NBIN2) scnt[tid] = 0;
    __syncthreads();
    const int i = blockIdx.x * BINTHREADS + tid;
    int b = -1, lpos = 0;
    float2 xv = make_float2(0.f, 0.f);
    if (i < n) {
        xv = reinterpret_cast<const float2*>(x)[i];
        b = bin_of(xv.y) * NBIN + bin_of(xv.x);
        lpos = atomicAdd(&scnt[b], 1);
    }
    __syncthreads();
    if (tid < NBIN2 && scnt[tid] > 0)
        sbase[tid] = atomicAdd(&g_fill[tid], scnt[tid]);
    __syncthreads();
    if (b >= 0) {
        const int pos = g_off[b] + sbase[b] + lpos;
        g_ptidx[pos] = i;
        g_px[pos]    = xv;
    }
}

// ---- 4: main GEMM ----
__global__ __launch_bounds__(NTHREADS, 2)
void image_features_bin_kernel(const float* __restrict__ sigma,
                               float* __restrict__ out)
{
    const int bid = blockIdx.x;
    if (bid >= g_nCta) return;

    extern __shared__ unsigned char smem[];
    const uint32_t sb = smem_u32(smem);

    const int tid  = threadIdx.x;
    const int lane = tid & 31;
    const int w    = tid >> 5;
    const int wm   = w >> 2;
    const int wn   = w & 3;

    const int4 inf = g_ctaInfo[bid];     // {start, end, wp, wq}
    const int start = inf.x;
    const int nloc  = inf.y - inf.x;
    const int wp = inf.z, wq = inf.w;

    float* xs   = reinterpret_cast<float*>(smem + OFF_XS);
    float* k0s  = reinterpret_cast<float*>(smem + OFF_K0);
    float* k1s  = reinterpret_cast<float*>(smem + OFF_K1);
    int*   sidx = reinterpret_cast<int*>(smem + OFF_IDX);

    // B gather: per f a contiguous 512B block; 4096 x 16B cp.async
    {
        const __half* vbase = g_Bvar + (size_t)(wq >> 1) * VARELEM + wp * WIN;
        #pragma unroll
        for (int j = 0; j < 8; j++) {
            const int u = tid + j * NTHREADS;
            const int f = u >> 5;
            const int c = u & 31;
            const uint32_t dst = sb + OFF_B + f * ROWB + (c >> 1) * 32 + (c & 1) * 16;
            CPASYNC16(dst, vbase + f * (PP * WIN) + c * 8);
        }
        asm volatile("cp.async.commit_group;" ::: "memory");
    }

    // point gather (coords packed by scatter; pad rows reuse last point)
    if (tid < 128) {
        const int pos = start + min(tid, nloc - 1);
        sidx[tid] = (tid < nloc) ? g_ptidx[pos] : -1;
        const float2 xv = g_px[pos];
        xs[2 * tid]     = xv.x;
        xs[2 * tid + 1] = xv.y;
    }

    const float ls  = __expf(sigma[0]);
    const float inv = 0.5f / (ls * ls);
    __syncthreads();   // xs visible

    // exp tables via recurrence: thread = (m, axis, half); 8 entries each
    {
        const int m    = tid & 127;
        const int axis = (tid >> 7) & 1;
        const int i0   = (tid >> 8) * 8;
        const int wnd  = axis ? wq : wp;
        const float xv = xs[2 * m + axis];
        const float d0 = (G0 + (float)(wnd + i0) * GH) - xv;
        const float S  = __expf(-2.0f * inv * GH * GH);
        float k = __expf(-inv * d0 * d0);
        float t = __expf(-inv * GH * (2.0f * d0 + GH));
        float* tab = (axis ? k1s : k0s) + i0 * 129 + m;
        #pragma unroll
        for (int i = 0; i < 8; i++) {
            tab[i * 129] = k;
            k *= t;
            t *= S;
        }
    }
    __syncthreads();   // tables visible

    // hoist k1 factors: per i-tile, rows m0/m1, col pairs (c0,c0+1),(c0+8,c0+9)
    const int mb = wm * 32 + (lane >> 2);
    const int c0 = (lane & 3) * 2;
    __half2 k1h[2][4];
    #pragma unroll
    for (int i = 0; i < 2; i++) {
        const int m0 = mb + i * 16, m1 = m0 + 8;
        k1h[i][0] = __floats2half2_rn(k1s[c0 * 129 + m0], k1s[(c0 + 1) * 129 + m0]);
        k1h[i][1] = __floats2half2_rn(k1s[c0 * 129 + m1], k1s[(c0 + 1) * 129 + m1]);
        k1h[i][2] = __floats2half2_rn(k1s[(c0 + 8) * 129 + m0], k1s[(c0 + 9) * 129 + m0]);
        k1h[i][3] = __floats2half2_rn(k1s[(c0 + 8) * 129 + m1], k1s[(c0 + 9) * 129 + m1]);
    }

    asm volatile("cp.async.wait_group 0;" ::: "memory");
    __syncthreads();   // B ready

    float acc[2][4][4];
    #pragma unroll
    for (int i = 0; i < 2; i++)
        #pragma unroll
        for (int j = 0; j < 4; j++)
            #pragma unroll
            for (int k = 0; k < 4; k++) acc[i][j][k] = 0.0f;

    const uint32_t sB = sb + OFF_B;
    const uint32_t aoff = (lane & 15) * ROWB + (((lane >> 4) << 3) * 2);

    #pragma unroll 4
    for (int s = 0; s < KSTEPS; s++) {
        uint32_t bh[2][4];
        #pragma unroll
        for (int g = 0; g < 2; g++) {
            const uint32_t ba = sB + (wn * 32 + g * 16) * ROWB + aoff + s * 32;
            LDSM4(bh[g][0], bh[g][1], bh[g][2], bh[g][3], ba);
        }
        const float* k0row = k0s + s * 129;
        #pragma unroll
        for (int i = 0; i < 2; i++) {
            const int m0 = mb + i * 16;
            const __half2 h0 = __float2half2_rn(k0row[m0]);
            const __half2 h1 = __float2half2_rn(k0row[m0 + 8]);
            const __half2 a0 = __hmul2(h0, k1h[i][0]);
            const __half2 a1 = __hmul2(h1, k1h[i][1]);
            const __half2 a2 = __hmul2(h0, k1h[i][2]);
            const __half2 a3 = __hmul2(h1, k1h[i][3]);
            const uint32_t u0 = *reinterpret_cast<const uint32_t*>(&a0);
            const uint32_t u1 = *reinterpret_cast<const uint32_t*>(&a1);
            const uint32_t u2 = *reinterpret_cast<const uint32_t*>(&a2);
            const uint32_t u3 = *reinterpret_cast<const uint32_t*>(&a3);
            #pragma unroll
            for (int j = 0; j < 4; j++) {
                const int jg = j >> 1, par = j & 1;
                MMA16816(acc[i][j], u0, u1, u2, u3, bh[jg][par], bh[jg][par + 2]);
            }
        }
    }

    // epilogue: scatter rows via sidx
    #pragma unroll
    for (int i = 0; i < 2; i++) {
        const int r0 = wm * 32 + i * 16 + (lane >> 2);
        const int g0 = sidx[r0];
        const int g1 = sidx[r0 + 8];
        #pragma unroll
        for (int j = 0; j < 4; j++) {
            const int col = wn * 32 + j * 8 + 2 * (lane & 3);
            if (g0 >= 0)
                *reinterpret_cast<float2*>(out + (size_t)g0 * FDIM + col) =
                    make_float2(acc[i][j][0], acc[i][j][1]);
            if (g1 >= 0)
                *reinterpret_cast<float2*>(out + (size_t)g1 * FDIM + col) =
                    make_float2(acc[i][j][2], acc[i][j][3]);
        }
    }
}

extern "C" void kernel_launch(void* const* d_in, const int* in_sizes, int n_in,
                              void* d_out, int out_size)
{
    const float* x     = (const float*)d_in[0];   // [B, N, 2]
    const float* sigma = (const float*)d_in[1];   // [1]
    const float* IF    = (const float*)d_in[2];   // [F, P, P]
    float* out         = (float*)d_out;           // [B*N, F]

    const int n = in_sizes[0] / 2;                // 131072

    cudaFuncSetAttribute(image_features_bin_kernel,
                         cudaFuncAttributeMaxDynamicSharedMemorySize, SMEM_TOT);

    zero_kernel<<<1, 256>>>();
    init_count_kernel<<<HISTBLOCKS + CONVBLOCKS, BINTHREADS>>>(IF, x, n);
    plan_kernel<<<1, 256>>>();
    scatter_kernel<<<(n + BINTHREADS - 1) / BINTHREADS, BINTHREADS>>>(x, n);
    image_features_bin_kernel<<<n / 128 + NBIN, NTHREADS, SMEM_TOT>>>(sigma, out);
}